// round 1
// baseline (speedup 1.0000x reference)
#include <cuda_runtime.h>

#define NN 8192
#define DD 64
#define EK 262144
#define EHK 262144

// Scratch (device globals: allocation-free)
__device__ float g_sk[NN * DD];   // normalized state_K
__device__ float g_g[NN];         // tanh(state_H)
__device__ float g_fK[NN * DD];   // f_K accumulator

__device__ __forceinline__ void red4(float* p, float a, float b, float c, float d) {
    asm volatile("red.global.add.v4.f32 [%0], {%1,%2,%3,%4};"
                 :: "l"(p), "f"(a), "f"(b), "f"(c), "f"(d) : "memory");
}

__device__ __forceinline__ float warp_sum(float v) {
    #pragma unroll
    for (int o = 16; o; o >>= 1) v += __shfl_xor_sync(0xFFFFFFFFu, v, o);
    return v;
}

// --- normalize state_K rows + g = tanh(state_H). warp-per-row, 4 rows/block.
__global__ void prep_kernel(const float* __restrict__ sH, const float* __restrict__ sK) {
    int warp = threadIdx.x >> 5, lane = threadIdx.x & 31;
    int row = blockIdx.x * 4 + warp;
    const float2* src = (const float2*)(sK + row * DD);
    float2 v = src[lane];
    float ss = warp_sum(v.x * v.x + v.y * v.y);
    float inv = rsqrtf(ss);
    ((float2*)(g_sk + row * DD))[lane] = make_float2(v.x * inv, v.y * inv);
    if (lane == 0) g_g[row] = tanhf(sH[row]);
}

// --- zero f_K accumulator (must run every launch: graph replays)
__global__ void zero_kernel() {
    int i = blockIdx.x * blockDim.x + threadIdx.x;
    ((float4*)g_fK)[i] = make_float4(0.f, 0.f, 0.f, 0.f);
}

// --- f_H = -state_H + W_H @ g.  One block (256 thr) per row, float4 loads.
__global__ void matvec_kernel(const float* __restrict__ sH,
                              const float* __restrict__ W,
                              float* __restrict__ fH) {
    int row = blockIdx.x;
    const float4* Wr = (const float4*)(W + (size_t)row * NN);
    const float4* g4 = (const float4*)g_g;
    float acc = 0.f;
    #pragma unroll
    for (int it = 0; it < 8; it++) {
        int k = threadIdx.x + it * 256;
        float4 w = __ldg(Wr + k);
        float4 g = g4[k];
        acc += w.x * g.x + w.y * g.y + w.z * g.z + w.w * g.w;
    }
    acc = warp_sum(acc);
    __shared__ float r[8];
    if ((threadIdx.x & 31) == 0) r[threadIdx.x >> 5] = acc;
    __syncthreads();
    if (threadIdx.x < 8) {
        float v = r[threadIdx.x];
        #pragma unroll
        for (int o = 4; o; o >>= 1) v += __shfl_xor_sync(0xFFu, v, o);
        if (threadIdx.x == 0) fH[row] = -sH[row] + v;
    }
}

// --- HK edges: Gram dot, f_H scatter, f_K scatter (-g_i g_j /2 * sk). warp/edge.
__global__ void edgeHK_kernel(const int* __restrict__ ind, float* __restrict__ fH) {
    int e = (blockIdx.x * blockDim.x + threadIdx.x) >> 5;
    int lane = threadIdx.x & 31;
    int2 ij = __ldg((const int2*)ind + e);
    int i = ij.x, j = ij.y;
    float2 a = ((const float2*)(g_sk + i * DD))[lane];
    float2 b = ((const float2*)(g_sk + j * DD))[lane];
    float gram = warp_sum(a.x * b.x + a.y * b.y);
    float gi = __ldg(g_g + i), gj = __ldg(g_g + j);
    if (lane == 0) {
        atomicAdd(fH + i, gram * gj * 0.5f);   // /KAPPA_H
        atomicAdd(fH + j, gram * gi * 0.5f);
    }
    float coef = -0.5f * gi * gj;              // -G/KAPPA_K
    int half = lane >> 4, l4 = lane & 15;
    int dstRow = half ? j : i;
    int srcRow = half ? i : j;
    float4 s = ((const float4*)(g_sk + srcRow * DD))[l4];
    red4(g_fK + dstRow * DD + l4 * 4, coef * s.x, coef * s.y, coef * s.z, coef * s.w);
}

// --- K edges: s = <sk_p, sk_q>, dE = sum_h tanh(s*w1+b1)*w2, scatter dE*sk.
__global__ void edgeK_kernel(const int* __restrict__ ind,
                             const float* __restrict__ w1,
                             const float* __restrict__ b1,
                             const float* __restrict__ w2) {
    int e = (blockIdx.x * blockDim.x + threadIdx.x) >> 5;
    int lane = threadIdx.x & 31;
    int2 pq = __ldg((const int2*)ind + e);
    int p = pq.x, q = pq.y;
    float2 a = ((const float2*)(g_sk + p * DD))[lane];
    float2 b = ((const float2*)(g_sk + q * DD))[lane];
    float s = warp_sum(a.x * b.x + a.y * b.y);
    float t0 = tanhf(s * __ldg(w1 + lane)      + __ldg(b1 + lane))      * __ldg(w2 + lane);
    float t1 = tanhf(s * __ldg(w1 + lane + 32) + __ldg(b1 + lane + 32)) * __ldg(w2 + lane + 32);
    float dE = warp_sum(t0 + t1);
    int half = lane >> 4, l4 = lane & 15;
    int dstRow = half ? q : p;
    int srcRow = half ? p : q;
    float4 v = ((const float4*)(g_sk + srcRow * DD))[l4];
    red4(g_fK + dstRow * DD + l4 * 4, dE * v.x, dE * v.y, dE * v.z, dE * v.w);
}

// --- finalize: f_K = -acc + sk*<sk,acc> + sk @ (omega-omega^T)/2.  warp/row.
__global__ void fin_kernel(const float* __restrict__ omega, float* __restrict__ out) {
    __shared__ float A[DD * DD];      // antisymmetrized omega
    __shared__ float srow[8 * DD];
    for (int k = threadIdx.x; k < DD * DD; k += 256) {
        int r = k >> 6, c = k & 63;
        A[k] = 0.5f * (omega[k] - omega[c * DD + r]);
    }
    __syncthreads();
    int warp = threadIdx.x >> 5, lane = threadIdx.x & 31;
    int row = blockIdx.x * 8 + warp;
    float2 skv = ((const float2*)(g_sk + row * DD))[lane];
    float2 fv  = ((const float2*)(g_fK + row * DD))[lane];
    float d = warp_sum(skv.x * fv.x + skv.y * fv.y);
    ((float2*)(srow + warp * DD))[lane] = skv;
    __syncwarp();
    const float* sr = srow + warp * DD;
    const float2* A2 = (const float2*)A;
    float m0 = 0.f, m1 = 0.f;
    #pragma unroll
    for (int k = 0; k < DD; k++) {
        float sv = sr[k];
        float2 av = A2[k * 32 + lane];
        m0 += sv * av.x;
        m1 += sv * av.y;
    }
    float o0 = -fv.x + skv.x * d + m0;
    float o1 = -fv.y + skv.y * d + m1;
    ((float2*)(out + NN + row * DD))[lane] = make_float2(o0, o1);
}

extern "C" void kernel_launch(void* const* d_in, const int* in_sizes, int n_in,
                              void* d_out, int out_size) {
    const float* sH   = (const float*)d_in[0];
    const float* sK   = (const float*)d_in[1];
    const float* WH   = (const float*)d_in[2];
    const float* om   = (const float*)d_in[3];
    const float* w1   = (const float*)d_in[4];
    const float* b1   = (const float*)d_in[5];
    const float* w2   = (const float*)d_in[6];
    const int*  indK  = (const int*)d_in[7];
    const int*  indHK = (const int*)d_in[8];
    float* out = (float*)d_out;

    prep_kernel<<<NN / 4, 128>>>(sH, sK);
    zero_kernel<<<(NN * DD / 4) / 256, 256>>>();
    matvec_kernel<<<NN, 256>>>(sH, WH, out);
    edgeHK_kernel<<<EHK / 8, 256>>>(indHK, out);
    edgeK_kernel<<<EK / 8, 256>>>(indK, w1, b1, w2);
    fin_kernel<<<NN / 8, 256>>>(om, out);
}

// round 2
// speedup vs baseline: 1.1259x; 1.1259x over previous
#include <cuda_runtime.h>

#define NN 8192
#define DD 64
#define EK 262144
#define EHK 262144

// Scratch (device globals: allocation-free)
__device__ float g_sk[NN * DD];   // normalized state_K
__device__ float g_g[NN];         // tanh(state_H)
__device__ float g_fK[NN * DD];   // f_K edge accumulator
__device__ float g_fHa[NN];       // f_H edge accumulator (decoupled from matvec)

__device__ __forceinline__ void red4(float* p, float a, float b, float c, float d) {
    asm volatile("red.global.add.v4.f32 [%0], {%1,%2,%3,%4};"
                 :: "l"(p), "f"(a), "f"(b), "f"(c), "f"(d) : "memory");
}

__device__ __forceinline__ float warp_sum(float v) {
    #pragma unroll
    for (int o = 16; o; o >>= 1) v += __shfl_xor_sync(0xFFFFFFFFu, v, o);
    return v;
}

// --- prep: normalize state_K rows (warp-per-row, 8/block), g=tanh(sH),
//     and zero both edge accumulators. 1024 blocks x 256 threads.
__global__ void prep_kernel(const float* __restrict__ sH, const float* __restrict__ sK) {
    int warp = threadIdx.x >> 5, lane = threadIdx.x & 31;
    int row = blockIdx.x * 8 + warp;
    float2 v = ((const float2*)(sK + row * DD))[lane];
    float ss = warp_sum(v.x * v.x + v.y * v.y);
    float inv = rsqrtf(ss);
    ((float2*)(g_sk + row * DD))[lane] = make_float2(v.x * inv, v.y * inv);
    if (lane == 0) g_g[row] = tanhf(sH[row]);
    int gt = blockIdx.x * 256 + threadIdx.x;          // 0..262143
    if (gt < NN * DD / 4) ((float4*)g_fK)[gt] = make_float4(0.f, 0.f, 0.f, 0.f);
    if (gt < NN / 4)      ((float4*)g_fHa)[gt] = make_float4(0.f, 0.f, 0.f, 0.f);
}

// --- mega kernel: matvec rows, HK edges and K edges interleaved 1:4:4.
//     73728 blocks of 256 threads; all three workloads independent.
__global__ __launch_bounds__(256, 6) void mega_kernel(
    const float* __restrict__ sH, const float* __restrict__ W,
    const float* __restrict__ w1, const float* __restrict__ b1,
    const float* __restrict__ w2,
    const int* __restrict__ indK, const int* __restrict__ indHK,
    float* __restrict__ out)
{
    __shared__ float rr[8];
    int grp = blockIdx.x / 9;
    int r   = blockIdx.x - grp * 9;
    int lane = threadIdx.x & 31, warp = threadIdx.x >> 5;

    if (r == 0) {
        // ---- matvec: f_H[grp] = -sH[grp] + W_H[grp,:] @ g  (streaming loads)
        const float4* Wr = (const float4*)(W + (size_t)grp * NN);
        const float4* g4 = (const float4*)g_g;
        float acc = 0.f;
        #pragma unroll
        for (int it = 0; it < 8; it++) {
            int k = threadIdx.x + it * 256;
            float4 w = __ldcs(Wr + k);     // stream: don't pollute L2
            float4 g = g4[k];
            acc += w.x * g.x + w.y * g.y + w.z * g.z + w.w * g.w;
        }
        acc = warp_sum(acc);
        if (lane == 0) rr[warp] = acc;
        __syncthreads();
        if (threadIdx.x == 0) {
            float v = rr[0] + rr[1] + rr[2] + rr[3] + rr[4] + rr[5] + rr[6] + rr[7];
            out[grp] = -sH[grp] + v;
        }
    } else if (r <= 4) {
        // ---- HK edge: warp-per-edge
        int e = (grp * 4 + (r - 1)) * 8 + warp;
        int2 ij = __ldg((const int2*)indHK + e);
        int i = ij.x, j = ij.y;
        float2 a = ((const float2*)(g_sk + i * DD))[lane];
        float2 b = ((const float2*)(g_sk + j * DD))[lane];
        float gram = warp_sum(a.x * b.x + a.y * b.y);
        float gi = __ldg(g_g + i), gj = __ldg(g_g + j);
        if (lane == 0) {
            atomicAdd(g_fHa + i, gram * gj * 0.5f);   // /KAPPA_H
            atomicAdd(g_fHa + j, gram * gi * 0.5f);
        }
        float coef = -0.5f * gi * gj;                 // -G/KAPPA_K
        int half = lane >> 4, l4 = lane & 15;
        int dstRow = half ? j : i;
        int srcRow = half ? i : j;
        float4 s = ((const float4*)(g_sk + srcRow * DD))[l4];
        red4(g_fK + dstRow * DD + l4 * 4, coef * s.x, coef * s.y, coef * s.z, coef * s.w);
    } else {
        // ---- K edge: warp-per-edge, MLP via per-lane tanh pair
        int e = (grp * 4 + (r - 5)) * 8 + warp;
        int2 pq = __ldg((const int2*)indK + e);
        int p = pq.x, q = pq.y;
        float2 a = ((const float2*)(g_sk + p * DD))[lane];
        float2 b = ((const float2*)(g_sk + q * DD))[lane];
        float s = warp_sum(a.x * b.x + a.y * b.y);
        float t0 = tanhf(s * __ldg(w1 + lane)      + __ldg(b1 + lane))      * __ldg(w2 + lane);
        float t1 = tanhf(s * __ldg(w1 + lane + 32) + __ldg(b1 + lane + 32)) * __ldg(w2 + lane + 32);
        float dE = warp_sum(t0 + t1);
        int half = lane >> 4, l4 = lane & 15;
        int dstRow = half ? q : p;
        int srcRow = half ? p : q;
        float4 v = ((const float4*)(g_sk + srcRow * DD))[l4];
        red4(g_fK + dstRow * DD + l4 * 4, dE * v.x, dE * v.y, dE * v.z, dE * v.w);
    }
}

// --- finalize: f_H += fHacc; f_K = -acc + sk*<sk,acc> + sk @ (omega-omega^T)/2.
__global__ void fin_kernel(const float* __restrict__ omega, float* __restrict__ out) {
    __shared__ float A[DD * DD];      // antisymmetrized omega
    __shared__ float srow[8 * DD];
    for (int k = threadIdx.x; k < DD * DD; k += 256) {
        int rI = k >> 6, c = k & 63;
        A[k] = 0.5f * (omega[k] - omega[c * DD + rI]);
    }
    __syncthreads();
    int warp = threadIdx.x >> 5, lane = threadIdx.x & 31;
    int row = blockIdx.x * 8 + warp;
    if (lane == 0) out[row] += g_fHa[row];            // finish f_H
    float2 skv = ((const float2*)(g_sk + row * DD))[lane];
    float2 fv  = ((const float2*)(g_fK + row * DD))[lane];
    float d = warp_sum(skv.x * fv.x + skv.y * fv.y);
    ((float2*)(srow + warp * DD))[lane] = skv;
    __syncwarp();
    const float* sr = srow + warp * DD;
    const float2* A2 = (const float2*)A;
    float m0 = 0.f, m1 = 0.f;
    #pragma unroll
    for (int k = 0; k < DD; k++) {
        float sv = sr[k];
        float2 av = A2[k * 32 + lane];
        m0 += sv * av.x;
        m1 += sv * av.y;
    }
    float o0 = -fv.x + skv.x * d + m0;
    float o1 = -fv.y + skv.y * d + m1;
    ((float2*)(out + NN + row * DD))[lane] = make_float2(o0, o1);
}

extern "C" void kernel_launch(void* const* d_in, const int* in_sizes, int n_in,
                              void* d_out, int out_size) {
    const float* sH   = (const float*)d_in[0];
    const float* sK   = (const float*)d_in[1];
    const float* WH   = (const float*)d_in[2];
    const float* om   = (const float*)d_in[3];
    const float* w1   = (const float*)d_in[4];
    const float* b1   = (const float*)d_in[5];
    const float* w2   = (const float*)d_in[6];
    const int*  indK  = (const int*)d_in[7];
    const int*  indHK = (const int*)d_in[8];
    float* out = (float*)d_out;

    prep_kernel<<<NN / 8, 256>>>(sH, sK);
    mega_kernel<<<9 * NN, 256>>>(sH, WH, w1, b1, w2, indK, indHK, out);
    fin_kernel<<<NN / 8, 256>>>(om, out);
}